// round 1
// baseline (speedup 1.0000x reference)
#include <cuda_runtime.h>
#include <math.h>

#define F 128
#define MAXN 100000

// Scratch (device globals: no runtime allocation allowed)
__device__ float g_wh_ref[(size_t)MAXN * F];
__device__ float g_wh_dir[(size_t)MAXN * F];
__device__ float g_s_ref[MAXN];
__device__ float g_t_ref[MAXN];
__device__ float g_s_dir[MAXN];
__device__ float g_t_dir[MAXN];

__device__ __forceinline__ float leakyf(float x) { return x >= 0.f ? x : 0.2f * x; }
__device__ __forceinline__ float sigmoidf_(float x) { return 1.0f / (1.0f + __expf(-x)); }

// ---------------------------------------------------------------------------
// Kernel 1: Wh = h @ W  (both W_ref and W_dir via blockIdx.y)
// Classic SGEMM: 128x128 block tile, 8x8 per thread, K=128, double-buffered.
// ---------------------------------------------------------------------------
__global__ __launch_bounds__(256, 2)
void gemm_kernel(const float* __restrict__ h,
                 const float* __restrict__ Wref,
                 const float* __restrict__ Wdir,
                 int N)
{
    const float* W = (blockIdx.y == 0) ? Wref : Wdir;
    float* out = (blockIdx.y == 0) ? g_wh_ref : g_wh_dir;
    const int m0 = blockIdx.x * 128;

    __shared__ float As[2][8][128];
    __shared__ float Bs[2][8][128];

    const int tid = threadIdx.x;
    const int row = tid & 127;     // A-load row within tile
    const int c   = tid >> 7;      // 0..1 (k sub-chunk of 4)
    const int bk  = tid >> 5;      // 0..7 (B-load k row)
    const int bn  = tid & 31;      // B-load col/4

    const int tx = tid & 15;
    const int ty = tid >> 4;

    float acc[8][8];
#pragma unroll
    for (int i = 0; i < 8; i++)
#pragma unroll
        for (int j = 0; j < 8; j++) acc[i][j] = 0.f;

    int row_g = m0 + row;
    if (row_g >= N) row_g = N - 1;  // clamp; epilogue predicates stores

    auto load = [&](int k0, int b) {
        float4 av = *reinterpret_cast<const float4*>(&h[(size_t)row_g * F + k0 + c * 4]);
        As[b][c * 4 + 0][row] = av.x;
        As[b][c * 4 + 1][row] = av.y;
        As[b][c * 4 + 2][row] = av.z;
        As[b][c * 4 + 3][row] = av.w;
        float4 bv = *reinterpret_cast<const float4*>(&W[(k0 + bk) * F + bn * 4]);
        *reinterpret_cast<float4*>(&Bs[b][bk][bn * 4]) = bv;
    };

    load(0, 0);
    __syncthreads();
    int buf = 0;
#pragma unroll
    for (int kt = 0; kt < 16; ++kt) {
        if (kt < 15) load((kt + 1) * 8, buf ^ 1);
#pragma unroll
        for (int k = 0; k < 8; k++) {
            float4 a0 = *reinterpret_cast<const float4*>(&As[buf][k][ty * 8]);
            float4 a1 = *reinterpret_cast<const float4*>(&As[buf][k][ty * 8 + 4]);
            float4 b0 = *reinterpret_cast<const float4*>(&Bs[buf][k][tx * 8]);
            float4 b1 = *reinterpret_cast<const float4*>(&Bs[buf][k][tx * 8 + 4]);
            float a_[8] = {a0.x, a0.y, a0.z, a0.w, a1.x, a1.y, a1.z, a1.w};
            float b_[8] = {b0.x, b0.y, b0.z, b0.w, b1.x, b1.y, b1.z, b1.w};
#pragma unroll
            for (int i = 0; i < 8; i++)
#pragma unroll
                for (int j = 0; j < 8; j++) acc[i][j] += a_[i] * b_[j];
        }
        __syncthreads();
        buf ^= 1;
    }

#pragma unroll
    for (int i = 0; i < 8; i++) {
        int r = m0 + ty * 8 + i;
        if (r < N) {
            float4 v0 = make_float4(acc[i][0], acc[i][1], acc[i][2], acc[i][3]);
            float4 v1 = make_float4(acc[i][4], acc[i][5], acc[i][6], acc[i][7]);
            *reinterpret_cast<float4*>(&out[(size_t)r * F + tx * 8])     = v0;
            *reinterpret_cast<float4*>(&out[(size_t)r * F + tx * 8 + 4]) = v1;
        }
    }
}

// ---------------------------------------------------------------------------
// Kernel 2: per-node attention scalars
//   s_ref = Wh_ref @ a_ref[:128],  t_ref = Wh_ref @ a_ref[128:]
//   s_dir = Wh_dir @ a_dir[:128],  t_dir = Wh_dir @ a_dir[128:]
// One warp per node.
// ---------------------------------------------------------------------------
__global__ __launch_bounds__(256)
void scalars_kernel(const float* __restrict__ a_ref,
                    const float* __restrict__ a_dir,
                    int N)
{
    int n = (blockIdx.x * blockDim.x + threadIdx.x) >> 5;
    int lane = threadIdx.x & 31;
    if (n >= N) return;

    float4 vr = *reinterpret_cast<const float4*>(&g_wh_ref[(size_t)n * F + lane * 4]);
    float4 vd = *reinterpret_cast<const float4*>(&g_wh_dir[(size_t)n * F + lane * 4]);
    float4 ars = *reinterpret_cast<const float4*>(&a_ref[lane * 4]);
    float4 arn = *reinterpret_cast<const float4*>(&a_ref[128 + lane * 4]);
    float4 ads = *reinterpret_cast<const float4*>(&a_dir[lane * 4]);
    float4 adn = *reinterpret_cast<const float4*>(&a_dir[128 + lane * 4]);

    float sr = vr.x * ars.x + vr.y * ars.y + vr.z * ars.z + vr.w * ars.w;
    float tr = vr.x * arn.x + vr.y * arn.y + vr.z * arn.z + vr.w * arn.w;
    float sd = vd.x * ads.x + vd.y * ads.y + vd.z * ads.z + vd.w * ads.w;
    float td = vd.x * adn.x + vd.y * adn.y + vd.z * adn.z + vd.w * adn.w;

#pragma unroll
    for (int off = 16; off; off >>= 1) {
        sr += __shfl_xor_sync(0xffffffffu, sr, off);
        tr += __shfl_xor_sync(0xffffffffu, tr, off);
        sd += __shfl_xor_sync(0xffffffffu, sd, off);
        td += __shfl_xor_sync(0xffffffffu, td, off);
    }
    if (lane == 0) {
        g_s_ref[n] = sr;
        g_t_ref[n] = tr;
        g_s_dir[n] = sd;
        g_t_dir[n] = td;
    }
}

// ---------------------------------------------------------------------------
// Kernel 3: fused attention + gather + sigmoid + average. One warp per node.
// ---------------------------------------------------------------------------
__global__ __launch_bounds__(256)
void gather_kernel(const int* __restrict__ ref_nb,   // [N,4,10]
                   const int* __restrict__ ref_cnt,  // [N,4]
                   const int* __restrict__ dir_nb,   // [N,32]
                   const int* __restrict__ dir_cnt,  // [N]
                   float* __restrict__ out,
                   int N)
{
    __shared__ float redsum[8][4];
    const unsigned FULL = 0xffffffffu;
    const int wid = threadIdx.x >> 5;
    const int lane = threadIdx.x & 31;
    const int n = (blockIdx.x * blockDim.x + threadIdx.x) >> 5;
    if (n >= N) return;

    // ---------------- ref branch: depth-wise mean of t over valid nbrs ------
    if (lane < 4) redsum[wid][lane] = 0.f;
    __syncwarp();

    int rc_l = (lane < 4) ? ref_cnt[n * 4 + lane] : 0;
    int rcv[4];
#pragma unroll
    for (int d = 0; d < 4; d++) rcv[d] = __shfl_sync(FULL, rc_l, d);

    // slot j = lane (0..31) and j = 32+lane for lanes 0..7
    const int d1 = lane / 10;
    const int k1 = lane - d1 * 10;
    int idx1 = ref_nb[(size_t)n * 40 + lane];
    bool v1 = (k1 < rcv[d1]);
    if (v1) atomicAdd(&redsum[wid][d1], g_t_ref[idx1]);

    int idx2 = 0;
    bool v2 = false;
    if (lane < 8) {
        idx2 = ref_nb[(size_t)n * 40 + 32 + lane];
        v2 = ((lane + 2) < rcv[3]);
        if (v2) atomicAdd(&redsum[wid][3], g_t_ref[idx2]);
    }
    __syncwarp();

    float sref = g_s_ref[n];
    float e[4];
#pragma unroll
    for (int d = 0; d < 4; d++) {
        float cnt = (float)max(rcv[d], 1);
        e[d] = leakyf(sref + redsum[wid][d] / cnt);
    }
    float m4 = fmaxf(fmaxf(e[0], e[1]), fmaxf(e[2], e[3]));
    float ex4[4];
    float den4 = 0.f;
#pragma unroll
    for (int d = 0; d < 4; d++) { ex4[d] = __expf(e[d] - m4); den4 += ex4[d]; }
    float wd[4];
#pragma unroll
    for (int d = 0; d < 4; d++) wd[d] = ex4[d] / (den4 * (float)max(rcv[d], 1));

    float w1 = v1 ? wd[d1] : 0.f;
    float w2 = v2 ? wd[3] : 0.f;

    // ---------------- dir branch attention ---------------------------------
    int dcnt = dir_cnt[n];
    int didx = dir_nb[(size_t)n * 32 + lane];
    bool dval = (lane < dcnt);
    float sdir = g_s_dir[n];
    float ed = dval ? leakyf(sdir + g_t_dir[didx]) : -INFINITY;
    float md = ed;
#pragma unroll
    for (int off = 16; off; off >>= 1) md = fmaxf(md, __shfl_xor_sync(FULL, md, off));
    float exd = dval ? __expf(ed - md) : 0.f;
    float dend = exd;
#pragma unroll
    for (int off = 16; off; off >>= 1) dend += __shfl_xor_sync(FULL, dend, off);
    float alpha = exd / dend;

    // ---------------- row gathers (skip zero-weight rows; warp-uniform) ----
    const int col = lane * 4;
    float4 aR = make_float4(0.f, 0.f, 0.f, 0.f);
    float4 aD = make_float4(0.f, 0.f, 0.f, 0.f);

    for (int k = 0; k < 32; k++) {
        float w = __shfl_sync(FULL, alpha, k);
        int id = __shfl_sync(FULL, didx, k);
        if (w != 0.f) {
            float4 v = *reinterpret_cast<const float4*>(&g_wh_dir[(size_t)id * F + col]);
            aD.x += w * v.x; aD.y += w * v.y; aD.z += w * v.z; aD.w += w * v.w;
        }
    }
    for (int k = 0; k < 32; k++) {
        float w = __shfl_sync(FULL, w1, k);
        int id = __shfl_sync(FULL, idx1, k);
        if (w != 0.f) {
            float4 v = *reinterpret_cast<const float4*>(&g_wh_ref[(size_t)id * F + col]);
            aR.x += w * v.x; aR.y += w * v.y; aR.z += w * v.z; aR.w += w * v.w;
        }
    }
    for (int k = 0; k < 8; k++) {
        float w = __shfl_sync(FULL, w2, k);
        int id = __shfl_sync(FULL, idx2, k);
        if (w != 0.f) {
            float4 v = *reinterpret_cast<const float4*>(&g_wh_ref[(size_t)id * F + col]);
            aR.x += w * v.x; aR.y += w * v.y; aR.z += w * v.z; aR.w += w * v.w;
        }
    }

    float4 o;
    o.x = 0.5f * (sigmoidf_(aR.x) + sigmoidf_(aD.x));
    o.y = 0.5f * (sigmoidf_(aR.y) + sigmoidf_(aD.y));
    o.z = 0.5f * (sigmoidf_(aR.z) + sigmoidf_(aD.z));
    o.w = 0.5f * (sigmoidf_(aR.w) + sigmoidf_(aD.w));
    *reinterpret_cast<float4*>(&out[(size_t)n * F + col]) = o;
}

// ---------------------------------------------------------------------------
extern "C" void kernel_launch(void* const* d_in, const int* in_sizes, int n_in,
                              void* d_out, int out_size)
{
    const float* h     = (const float*)d_in[0];
    const float* W_ref = (const float*)d_in[1];
    const float* a_ref = (const float*)d_in[2];
    const float* W_dir = (const float*)d_in[3];
    const float* a_dir = (const float*)d_in[4];
    const int* ref_nb  = (const int*)d_in[5];
    const int* ref_cnt = (const int*)d_in[6];
    const int* dir_nb  = (const int*)d_in[7];
    const int* dir_cnt = (const int*)d_in[8];
    float* out = (float*)d_out;

    const int N = in_sizes[0] / F;

    dim3 g1((N + 127) / 128, 2);
    gemm_kernel<<<g1, 256>>>(h, W_ref, W_dir, N);

    const int nwb = (N * 32 + 255) / 256;  // one warp per node
    scalars_kernel<<<nwb, 256>>>(a_ref, a_dir, N);
    gather_kernel<<<nwb, 256>>>(ref_nb, ref_cnt, dir_nb, dir_cnt, out, N);
}

// round 2
// speedup vs baseline: 1.3010x; 1.3010x over previous
#include <cuda_runtime.h>
#include <math.h>
#include <stdint.h>

#define F 128
#define MAXN 100000

// Scratch (device globals: no runtime allocation allowed)
__device__ float g_wh_ref[(size_t)MAXN * F];
__device__ float g_wh_dir[(size_t)MAXN * F];
__device__ float g_s_ref[MAXN];
__device__ float g_t_ref[MAXN];
__device__ float g_s_dir[MAXN];
__device__ float g_t_dir[MAXN];

__device__ __forceinline__ float leakyf(float x) { return x >= 0.f ? x : 0.2f * x; }
__device__ __forceinline__ float sigmoidf_(float x) { return 1.0f / (1.0f + __expf(-x)); }

__device__ __forceinline__ uint32_t f2tf32(float f) {
    uint32_t u;
    asm("cvt.rna.tf32.f32 %0, %1;" : "=r"(u) : "f"(f));
    return u;
}

__device__ __forceinline__ void mma_tf32(float& c0, float& c1, float& c2, float& c3,
                                         uint32_t a0, uint32_t a1, uint32_t a2, uint32_t a3,
                                         uint32_t b0, uint32_t b1) {
    asm volatile(
        "mma.sync.aligned.m16n8k8.row.col.f32.tf32.tf32.f32 "
        "{%0,%1,%2,%3},{%4,%5,%6,%7},{%8,%9},{%0,%1,%2,%3};"
        : "+f"(c0), "+f"(c1), "+f"(c2), "+f"(c3)
        : "r"(a0), "r"(a1), "r"(a2), "r"(a3), "r"(b0), "r"(b1));
}

// ---------------------------------------------------------------------------
// Kernel 1: Wh = h @ W via tf32 tensor cores.
// Block tile 128x128, BK=16, 8 warps (4m x 2n), warp tile 32x64.
// Smem stored [k][m]/[k][n] with stride 132 (pad 4) for conflict-free LDS.
// ---------------------------------------------------------------------------
#define BK 16
#define LDS_STRIDE 132

__global__ __launch_bounds__(256, 2)
void gemm_tf32_kernel(const float* __restrict__ h,
                      const float* __restrict__ Wref,
                      const float* __restrict__ Wdir,
                      int N)
{
    const float* W = (blockIdx.y == 0) ? Wref : Wdir;
    float* out = (blockIdx.y == 0) ? g_wh_ref : g_wh_dir;
    const int m0 = blockIdx.x * 128;

    __shared__ uint32_t As[2][BK][LDS_STRIDE];  // [k][m]
    __shared__ uint32_t Bs[2][BK][LDS_STRIDE];  // [k][n]

    const int tid = threadIdx.x;
    const int warp = tid >> 5;
    const int lane = tid & 31;
    const int gid = lane >> 2;   // group id 0..7
    const int tig = lane & 3;    // thread in group 0..3
    const int wm = warp & 3;     // warp m band (0..3) -> rows wm*32
    const int wn = warp >> 2;    // warp n band (0..1) -> cols wn*64

    // accumulators: 2 m-tiles x 8 n-tiles x 4 regs
    float acc[2][8][4];
#pragma unroll
    for (int i = 0; i < 2; i++)
#pragma unroll
        for (int j = 0; j < 8; j++)
#pragma unroll
            for (int r = 0; r < 4; r++) acc[i][j][r] = 0.f;

    // ---- global load helpers (each thread: 2x float4 A, 2x float4 B) ----
    // A: idx = tid + rep*256; row = idx&127, k4 = idx>>7 (0..3)
    // B: idx = tid + rep*256; kr = idx>>5 (0..15), n4 = idx&31
    int arow[2], ak4[2], bkr[2], bn4[2];
#pragma unroll
    for (int rep = 0; rep < 2; rep++) {
        int idx = tid + rep * 256;
        arow[rep] = idx & 127;
        ak4[rep] = idx >> 7;
        bkr[rep] = idx >> 5;
        bn4[rep] = idx & 31;
    }
    int arow_g[2];
#pragma unroll
    for (int rep = 0; rep < 2; rep++) {
        int r = m0 + arow[rep];
        arow_g[rep] = (r < N) ? r : (N - 1);
    }

    float4 aldg[2], bldg[2];
    auto issue_ldg = [&](int kt) {
#pragma unroll
        for (int rep = 0; rep < 2; rep++) {
            aldg[rep] = *reinterpret_cast<const float4*>(
                &h[(size_t)arow_g[rep] * F + kt * BK + ak4[rep] * 4]);
            bldg[rep] = *reinterpret_cast<const float4*>(
                &W[(size_t)(kt * BK + bkr[rep]) * F + bn4[rep] * 4]);
        }
    };
    auto sts = [&](int buf) {
#pragma unroll
        for (int rep = 0; rep < 2; rep++) {
            int kb = ak4[rep] * 4;
            As[buf][kb + 0][arow[rep]] = f2tf32(aldg[rep].x);
            As[buf][kb + 1][arow[rep]] = f2tf32(aldg[rep].y);
            As[buf][kb + 2][arow[rep]] = f2tf32(aldg[rep].z);
            As[buf][kb + 3][arow[rep]] = f2tf32(aldg[rep].w);
            uint4 bu;
            bu.x = f2tf32(bldg[rep].x);
            bu.y = f2tf32(bldg[rep].y);
            bu.z = f2tf32(bldg[rep].z);
            bu.w = f2tf32(bldg[rep].w);
            *reinterpret_cast<uint4*>(&Bs[buf][bkr[rep]][bn4[rep] * 4]) = bu;
        }
    };

    issue_ldg(0);
    sts(0);
    __syncthreads();

    int buf = 0;
#pragma unroll
    for (int kt = 0; kt < F / BK; ++kt) {
        if (kt < F / BK - 1) issue_ldg(kt + 1);

#pragma unroll
        for (int ks = 0; ks < 2; ks++) {
            const int kk = ks * 8;
            // A fragments for 2 m-tiles
            uint32_t afr[2][4];
#pragma unroll
            for (int mt = 0; mt < 2; mt++) {
                int mb = wm * 32 + mt * 16;
                afr[mt][0] = As[buf][kk + tig][mb + gid];
                afr[mt][1] = As[buf][kk + tig][mb + gid + 8];
                afr[mt][2] = As[buf][kk + tig + 4][mb + gid];
                afr[mt][3] = As[buf][kk + tig + 4][mb + gid + 8];
            }
#pragma unroll
            for (int nt = 0; nt < 8; nt++) {
                int nb = wn * 64 + nt * 8;
                uint32_t b0 = Bs[buf][kk + tig][nb + gid];
                uint32_t b1 = Bs[buf][kk + tig + 4][nb + gid];
#pragma unroll
                for (int mt = 0; mt < 2; mt++) {
                    mma_tf32(acc[mt][nt][0], acc[mt][nt][1], acc[mt][nt][2], acc[mt][nt][3],
                             afr[mt][0], afr[mt][1], afr[mt][2], afr[mt][3], b0, b1);
                }
            }
        }

        if (kt < F / BK - 1) {
            sts(buf ^ 1);
            __syncthreads();
            buf ^= 1;
        }
    }

    // ---- epilogue: D tile m16n8: c0 (gid, tig*2), c1 (gid, tig*2+1),
    //                              c2 (gid+8, tig*2), c3 (gid+8, tig*2+1)
#pragma unroll
    for (int mt = 0; mt < 2; mt++) {
        int r0 = m0 + wm * 32 + mt * 16 + gid;
        int r1 = r0 + 8;
#pragma unroll
        for (int nt = 0; nt < 8; nt++) {
            int col = wn * 64 + nt * 8 + tig * 2;
            if (r0 < N) {
                float2 v = make_float2(acc[mt][nt][0], acc[mt][nt][1]);
                *reinterpret_cast<float2*>(&out[(size_t)r0 * F + col]) = v;
            }
            if (r1 < N) {
                float2 v = make_float2(acc[mt][nt][2], acc[mt][nt][3]);
                *reinterpret_cast<float2*>(&out[(size_t)r1 * F + col]) = v;
            }
        }
    }
}

// ---------------------------------------------------------------------------
// Kernel 2: per-node attention scalars
// ---------------------------------------------------------------------------
__global__ __launch_bounds__(256)
void scalars_kernel(const float* __restrict__ a_ref,
                    const float* __restrict__ a_dir,
                    int N)
{
    int n = (blockIdx.x * blockDim.x + threadIdx.x) >> 5;
    int lane = threadIdx.x & 31;
    if (n >= N) return;

    float4 vr = *reinterpret_cast<const float4*>(&g_wh_ref[(size_t)n * F + lane * 4]);
    float4 vd = *reinterpret_cast<const float4*>(&g_wh_dir[(size_t)n * F + lane * 4]);
    float4 ars = *reinterpret_cast<const float4*>(&a_ref[lane * 4]);
    float4 arn = *reinterpret_cast<const float4*>(&a_ref[128 + lane * 4]);
    float4 ads = *reinterpret_cast<const float4*>(&a_dir[lane * 4]);
    float4 adn = *reinterpret_cast<const float4*>(&a_dir[128 + lane * 4]);

    float sr = vr.x * ars.x + vr.y * ars.y + vr.z * ars.z + vr.w * ars.w;
    float tr = vr.x * arn.x + vr.y * arn.y + vr.z * arn.z + vr.w * arn.w;
    float sd = vd.x * ads.x + vd.y * ads.y + vd.z * ads.z + vd.w * ads.w;
    float td = vd.x * adn.x + vd.y * adn.y + vd.z * adn.z + vd.w * adn.w;

#pragma unroll
    for (int off = 16; off; off >>= 1) {
        sr += __shfl_xor_sync(0xffffffffu, sr, off);
        tr += __shfl_xor_sync(0xffffffffu, tr, off);
        sd += __shfl_xor_sync(0xffffffffu, sd, off);
        td += __shfl_xor_sync(0xffffffffu, td, off);
    }
    if (lane == 0) {
        g_s_ref[n] = sr;
        g_t_ref[n] = tr;
        g_s_dir[n] = sd;
        g_t_dir[n] = td;
    }
}

// ---------------------------------------------------------------------------
// Kernel 3: fused attention + gather + sigmoid + average. One warp per node.
// ---------------------------------------------------------------------------
__global__ __launch_bounds__(256)
void gather_kernel(const int* __restrict__ ref_nb,   // [N,4,10]
                   const int* __restrict__ ref_cnt,  // [N,4]
                   const int* __restrict__ dir_nb,   // [N,32]
                   const int* __restrict__ dir_cnt,  // [N]
                   float* __restrict__ out,
                   int N)
{
    __shared__ float redsum[8][4];
    const unsigned FULL = 0xffffffffu;
    const int wid = threadIdx.x >> 5;
    const int lane = threadIdx.x & 31;
    const int n = (blockIdx.x * blockDim.x + threadIdx.x) >> 5;
    if (n >= N) return;

    // ---------------- ref branch: depth-wise mean of t over valid nbrs ------
    if (lane < 4) redsum[wid][lane] = 0.f;
    __syncwarp();

    int rc_l = (lane < 4) ? ref_cnt[n * 4 + lane] : 0;
    int rcv[4];
#pragma unroll
    for (int d = 0; d < 4; d++) rcv[d] = __shfl_sync(FULL, rc_l, d);

    const int d1 = lane / 10;
    const int k1 = lane - d1 * 10;
    int idx1 = ref_nb[(size_t)n * 40 + lane];
    bool v1 = (k1 < rcv[d1]);
    if (v1) atomicAdd(&redsum[wid][d1], g_t_ref[idx1]);

    int idx2 = 0;
    bool v2 = false;
    if (lane < 8) {
        idx2 = ref_nb[(size_t)n * 40 + 32 + lane];
        v2 = ((lane + 2) < rcv[3]);
        if (v2) atomicAdd(&redsum[wid][3], g_t_ref[idx2]);
    }
    __syncwarp();

    float sref = g_s_ref[n];
    float e[4];
#pragma unroll
    for (int d = 0; d < 4; d++) {
        float cnt = (float)max(rcv[d], 1);
        e[d] = leakyf(sref + redsum[wid][d] / cnt);
    }
    float m4 = fmaxf(fmaxf(e[0], e[1]), fmaxf(e[2], e[3]));
    float ex4[4];
    float den4 = 0.f;
#pragma unroll
    for (int d = 0; d < 4; d++) { ex4[d] = __expf(e[d] - m4); den4 += ex4[d]; }
    float wd[4];
#pragma unroll
    for (int d = 0; d < 4; d++) wd[d] = ex4[d] / (den4 * (float)max(rcv[d], 1));

    float w1 = v1 ? wd[d1] : 0.f;
    float w2 = v2 ? wd[3] : 0.f;

    // ---------------- dir branch attention ---------------------------------
    int dcnt = dir_cnt[n];
    int didx = dir_nb[(size_t)n * 32 + lane];
    bool dval = (lane < dcnt);
    float sdir = g_s_dir[n];
    float ed = dval ? leakyf(sdir + g_t_dir[didx]) : -INFINITY;
    float md = ed;
#pragma unroll
    for (int off = 16; off; off >>= 1) md = fmaxf(md, __shfl_xor_sync(FULL, md, off));
    float exd = dval ? __expf(ed - md) : 0.f;
    float dend = exd;
#pragma unroll
    for (int off = 16; off; off >>= 1) dend += __shfl_xor_sync(FULL, dend, off);
    float alpha = exd / dend;

    // ---------------- row gathers (skip zero-weight rows; warp-uniform) ----
    const int col = lane * 4;
    float4 aR = make_float4(0.f, 0.f, 0.f, 0.f);
    float4 aD = make_float4(0.f, 0.f, 0.f, 0.f);

    for (int k = 0; k < 32; k++) {
        float w = __shfl_sync(FULL, alpha, k);
        int id = __shfl_sync(FULL, didx, k);
        if (w != 0.f) {
            float4 v = *reinterpret_cast<const float4*>(&g_wh_dir[(size_t)id * F + col]);
            aD.x += w * v.x; aD.y += w * v.y; aD.z += w * v.z; aD.w += w * v.w;
        }
    }
    for (int k = 0; k < 32; k++) {
        float w = __shfl_sync(FULL, w1, k);
        int id = __shfl_sync(FULL, idx1, k);
        if (w != 0.f) {
            float4 v = *reinterpret_cast<const float4*>(&g_wh_ref[(size_t)id * F + col]);
            aR.x += w * v.x; aR.y += w * v.y; aR.z += w * v.z; aR.w += w * v.w;
        }
    }
    for (int k = 0; k < 8; k++) {
        float w = __shfl_sync(FULL, w2, k);
        int id = __shfl_sync(FULL, idx2, k);
        if (w != 0.f) {
            float4 v = *reinterpret_cast<const float4*>(&g_wh_ref[(size_t)id * F + col]);
            aR.x += w * v.x; aR.y += w * v.y; aR.z += w * v.z; aR.w += w * v.w;
        }
    }

    float4 o;
    o.x = 0.5f * (sigmoidf_(aR.x) + sigmoidf_(aD.x));
    o.y = 0.5f * (sigmoidf_(aR.y) + sigmoidf_(aD.y));
    o.z = 0.5f * (sigmoidf_(aR.z) + sigmoidf_(aD.z));
    o.w = 0.5f * (sigmoidf_(aR.w) + sigmoidf_(aD.w));
    *reinterpret_cast<float4*>(&out[(size_t)n * F + col]) = o;
}

// ---------------------------------------------------------------------------
extern "C" void kernel_launch(void* const* d_in, const int* in_sizes, int n_in,
                              void* d_out, int out_size)
{
    const float* h     = (const float*)d_in[0];
    const float* W_ref = (const float*)d_in[1];
    const float* a_ref = (const float*)d_in[2];
    const float* W_dir = (const float*)d_in[3];
    const float* a_dir = (const float*)d_in[4];
    const int* ref_nb  = (const int*)d_in[5];
    const int* ref_cnt = (const int*)d_in[6];
    const int* dir_nb  = (const int*)d_in[7];
    const int* dir_cnt = (const int*)d_in[8];
    float* out = (float*)d_out;

    const int N = in_sizes[0] / F;

    dim3 g1((N + 127) / 128, 2);
    gemm_tf32_kernel<<<g1, 256>>>(h, W_ref, W_dir, N);

    const int nwb = (N * 32 + 255) / 256;  // one warp per node
    scalars_kernel<<<nwb, 256>>>(a_ref, a_dir, N);
    gather_kernel<<<nwb, 256>>>(ref_nb, ref_cnt, dir_nb, dir_cnt, out, N);
}

// round 3
// speedup vs baseline: 1.4763x; 1.1347x over previous
#include <cuda_runtime.h>
#include <cuda_bf16.h>
#include <math.h>
#include <stdint.h>

#define F 128
#define MAXN 100000

// Scratch (device globals: no runtime allocation allowed)
// Wh tables stored as bf16 (2 bf16 per uint32): row = 64 uint32 = 256 B
__device__ uint32_t g_whb_ref[(size_t)MAXN * 64];
__device__ uint32_t g_whb_dir[(size_t)MAXN * 64];
__device__ float g_s_ref[MAXN];
__device__ float g_t_ref[MAXN];
__device__ float g_s_dir[MAXN];
__device__ float g_t_dir[MAXN];

__device__ __forceinline__ float leakyf(float x) { return x >= 0.f ? x : 0.2f * x; }
__device__ __forceinline__ float sigmoidf_(float x) { return 1.0f / (1.0f + __expf(-x)); }

__device__ __forceinline__ uint32_t f2tf32(float f) {
    uint32_t u;
    asm("cvt.rna.tf32.f32 %0, %1;" : "=r"(u) : "f"(f));
    return u;
}

__device__ __forceinline__ void mma_tf32(float& c0, float& c1, float& c2, float& c3,
                                         uint32_t a0, uint32_t a1, uint32_t a2, uint32_t a3,
                                         uint32_t b0, uint32_t b1) {
    asm volatile(
        "mma.sync.aligned.m16n8k8.row.col.f32.tf32.tf32.f32 "
        "{%0,%1,%2,%3},{%4,%5,%6,%7},{%8,%9},{%0,%1,%2,%3};"
        : "+f"(c0), "+f"(c1), "+f"(c2), "+f"(c3)
        : "r"(a0), "r"(a1), "r"(a2), "r"(a3), "r"(b0), "r"(b1));
}

// ---------------------------------------------------------------------------
// Kernel 1: Wh = h @ W via tf32 tensor cores. Epilogue:
//   - stores Wh as bf16x2
//   - computes s = Wh@a_self, t = Wh@a_nbr per row (fused scalars)
// Block tile 128x128, BK=16, 8 warps (4m x 2n), warp tile 32x64.
// ---------------------------------------------------------------------------
#define BK 16
#define LDS_STRIDE 132

__global__ __launch_bounds__(256, 2)
void gemm_tf32_kernel(const float* __restrict__ h,
                      const float* __restrict__ Wref,
                      const float* __restrict__ Wdir,
                      const float* __restrict__ a_ref,
                      const float* __restrict__ a_dir,
                      int N)
{
    const int by = blockIdx.y;
    const float* W = (by == 0) ? Wref : Wdir;
    const float* av = (by == 0) ? a_ref : a_dir;
    uint32_t* outb = (by == 0) ? g_whb_ref : g_whb_dir;
    const int m0 = blockIdx.x * 128;

    __shared__ uint32_t As[2][BK][LDS_STRIDE];  // [k][m]
    __shared__ uint32_t Bs[2][BK][LDS_STRIDE];  // [k][n]
    __shared__ float s_sm[128];
    __shared__ float t_sm[128];

    const int tid = threadIdx.x;
    const int warp = tid >> 5;
    const int lane = tid & 31;
    const int gid = lane >> 2;   // group id 0..7
    const int tig = lane & 3;    // thread in group 0..3
    const int wm = warp & 3;     // warp m band (0..3) -> rows wm*32
    const int wn = warp >> 2;    // warp n band (0..1) -> cols wn*64

    if (tid < 128) { s_sm[tid] = 0.f; t_sm[tid] = 0.f; }

    float acc[2][8][4];
#pragma unroll
    for (int i = 0; i < 2; i++)
#pragma unroll
        for (int j = 0; j < 8; j++)
#pragma unroll
            for (int r = 0; r < 4; r++) acc[i][j][r] = 0.f;

    int arow[2], ak4[2], bkr[2], bn4[2];
#pragma unroll
    for (int rep = 0; rep < 2; rep++) {
        int idx = tid + rep * 256;
        arow[rep] = idx & 127;
        ak4[rep] = idx >> 7;
        bkr[rep] = idx >> 5;
        bn4[rep] = idx & 31;
    }
    int arow_g[2];
#pragma unroll
    for (int rep = 0; rep < 2; rep++) {
        int r = m0 + arow[rep];
        arow_g[rep] = (r < N) ? r : (N - 1);
    }

    float4 aldg[2], bldg[2];
    auto issue_ldg = [&](int kt) {
#pragma unroll
        for (int rep = 0; rep < 2; rep++) {
            aldg[rep] = *reinterpret_cast<const float4*>(
                &h[(size_t)arow_g[rep] * F + kt * BK + ak4[rep] * 4]);
            bldg[rep] = *reinterpret_cast<const float4*>(
                &W[(size_t)(kt * BK + bkr[rep]) * F + bn4[rep] * 4]);
        }
    };
    auto sts = [&](int buf) {
#pragma unroll
        for (int rep = 0; rep < 2; rep++) {
            int kb = ak4[rep] * 4;
            As[buf][kb + 0][arow[rep]] = f2tf32(aldg[rep].x);
            As[buf][kb + 1][arow[rep]] = f2tf32(aldg[rep].y);
            As[buf][kb + 2][arow[rep]] = f2tf32(aldg[rep].z);
            As[buf][kb + 3][arow[rep]] = f2tf32(aldg[rep].w);
            uint4 bu;
            bu.x = f2tf32(bldg[rep].x);
            bu.y = f2tf32(bldg[rep].y);
            bu.z = f2tf32(bldg[rep].z);
            bu.w = f2tf32(bldg[rep].w);
            *reinterpret_cast<uint4*>(&Bs[buf][bkr[rep]][bn4[rep] * 4]) = bu;
        }
    };

    issue_ldg(0);
    sts(0);
    __syncthreads();

    int buf = 0;
#pragma unroll
    for (int kt = 0; kt < F / BK; ++kt) {
        if (kt < F / BK - 1) issue_ldg(kt + 1);

#pragma unroll
        for (int ks = 0; ks < 2; ks++) {
            const int kk = ks * 8;
            uint32_t afr[2][4];
#pragma unroll
            for (int mt = 0; mt < 2; mt++) {
                int mb = wm * 32 + mt * 16;
                afr[mt][0] = As[buf][kk + tig][mb + gid];
                afr[mt][1] = As[buf][kk + tig][mb + gid + 8];
                afr[mt][2] = As[buf][kk + tig + 4][mb + gid];
                afr[mt][3] = As[buf][kk + tig + 4][mb + gid + 8];
            }
#pragma unroll
            for (int nt = 0; nt < 8; nt++) {
                int nb = wn * 64 + nt * 8;
                uint32_t b0 = Bs[buf][kk + tig][nb + gid];
                uint32_t b1 = Bs[buf][kk + tig + 4][nb + gid];
#pragma unroll
                for (int mt = 0; mt < 2; mt++) {
                    mma_tf32(acc[mt][nt][0], acc[mt][nt][1], acc[mt][nt][2], acc[mt][nt][3],
                             afr[mt][0], afr[mt][1], afr[mt][2], afr[mt][3], b0, b1);
                }
            }
        }

        if (kt < F / BK - 1) {
            sts(buf ^ 1);
            __syncthreads();
            buf ^= 1;
        }
    }

    // ---- epilogue: bf16 store + fused per-row scalar dots ----
    float sp[2][2] = {{0.f, 0.f}, {0.f, 0.f}};
    float tp[2][2] = {{0.f, 0.f}, {0.f, 0.f}};

#pragma unroll
    for (int mt = 0; mt < 2; mt++) {
        int r0 = m0 + wm * 32 + mt * 16 + gid;
        int r1 = r0 + 8;
#pragma unroll
        for (int nt = 0; nt < 8; nt++) {
            int col = wn * 64 + nt * 8 + tig * 2;
            float as0 = av[col], as1 = av[col + 1];
            float an0 = av[128 + col], an1 = av[128 + col + 1];
            float c0 = acc[mt][nt][0], c1 = acc[mt][nt][1];
            float c2 = acc[mt][nt][2], c3 = acc[mt][nt][3];
            sp[mt][0] += c0 * as0 + c1 * as1;
            tp[mt][0] += c0 * an0 + c1 * an1;
            sp[mt][1] += c2 * as0 + c3 * as1;
            tp[mt][1] += c2 * an0 + c3 * an1;
            if (r0 < N) {
                __nv_bfloat162 p = __float22bfloat162_rn(make_float2(c0, c1));
                outb[(size_t)r0 * 64 + (col >> 1)] = *reinterpret_cast<uint32_t*>(&p);
            }
            if (r1 < N) {
                __nv_bfloat162 p = __float22bfloat162_rn(make_float2(c2, c3));
                outb[(size_t)r1 * 64 + (col >> 1)] = *reinterpret_cast<uint32_t*>(&p);
            }
        }
    }

    // reduce over tig lanes (lane bits 0,1), then shared-atomic across n-warps
#pragma unroll
    for (int mt = 0; mt < 2; mt++)
#pragma unroll
        for (int rr = 0; rr < 2; rr++) {
#pragma unroll
            for (int off = 1; off <= 2; off <<= 1) {
                sp[mt][rr] += __shfl_xor_sync(0xffffffffu, sp[mt][rr], off);
                tp[mt][rr] += __shfl_xor_sync(0xffffffffu, tp[mt][rr], off);
            }
            if (tig == 0) {
                int lr = wm * 32 + mt * 16 + gid + rr * 8;
                atomicAdd(&s_sm[lr], sp[mt][rr]);
                atomicAdd(&t_sm[lr], tp[mt][rr]);
            }
        }
    __syncthreads();

    if (tid < 128) {
        int gr = m0 + tid;
        if (gr < N) {
            if (by == 0) { g_s_ref[gr] = s_sm[tid]; g_t_ref[gr] = t_sm[tid]; }
            else         { g_s_dir[gr] = s_sm[tid]; g_t_dir[gr] = t_sm[tid]; }
        }
    }
}

// ---------------------------------------------------------------------------
// Kernel 2: fused attention + gather (bf16 rows) + sigmoid + average.
// One warp per node.
// ---------------------------------------------------------------------------
__global__ __launch_bounds__(256)
void gather_kernel(const int* __restrict__ ref_nb,   // [N,4,10]
                   const int* __restrict__ ref_cnt,  // [N,4]
                   const int* __restrict__ dir_nb,   // [N,32]
                   const int* __restrict__ dir_cnt,  // [N]
                   float* __restrict__ out,
                   int N)
{
    __shared__ float redsum[8][4];
    const unsigned FULL = 0xffffffffu;
    const int wid = threadIdx.x >> 5;
    const int lane = threadIdx.x & 31;
    const int n = (blockIdx.x * blockDim.x + threadIdx.x) >> 5;
    if (n >= N) return;

    // ---------------- ref branch: depth-wise mean of t over valid nbrs ------
    if (lane < 4) redsum[wid][lane] = 0.f;
    __syncwarp();

    int rc_l = (lane < 4) ? ref_cnt[n * 4 + lane] : 0;
    int rcv[4];
#pragma unroll
    for (int d = 0; d < 4; d++) rcv[d] = __shfl_sync(FULL, rc_l, d);

    const int d1 = lane / 10;
    const int k1 = lane - d1 * 10;
    int idx1 = ref_nb[(size_t)n * 40 + lane];
    bool v1 = (k1 < rcv[d1]);
    if (v1) atomicAdd(&redsum[wid][d1], g_t_ref[idx1]);

    int idx2 = 0;
    bool v2 = false;
    if (lane < 8) {
        idx2 = ref_nb[(size_t)n * 40 + 32 + lane];
        v2 = ((lane + 2) < rcv[3]);
        if (v2) atomicAdd(&redsum[wid][3], g_t_ref[idx2]);
    }
    __syncwarp();

    float sref = g_s_ref[n];
    float e[4];
#pragma unroll
    for (int d = 0; d < 4; d++) {
        float cnt = (float)max(rcv[d], 1);
        e[d] = leakyf(sref + redsum[wid][d] / cnt);
    }
    float m4 = fmaxf(fmaxf(e[0], e[1]), fmaxf(e[2], e[3]));
    float ex4[4];
    float den4 = 0.f;
#pragma unroll
    for (int d = 0; d < 4; d++) { ex4[d] = __expf(e[d] - m4); den4 += ex4[d]; }
    float wd[4];
#pragma unroll
    for (int d = 0; d < 4; d++) wd[d] = ex4[d] / (den4 * (float)max(rcv[d], 1));

    float w1 = v1 ? wd[d1] : 0.f;
    float w2 = v2 ? wd[3] : 0.f;

    // ---------------- dir branch attention ---------------------------------
    int dcnt = dir_cnt[n];
    int didx = dir_nb[(size_t)n * 32 + lane];
    bool dval = (lane < dcnt);
    float sdir = g_s_dir[n];
    float ed = dval ? leakyf(sdir + g_t_dir[didx]) : -INFINITY;
    float md = ed;
#pragma unroll
    for (int off = 16; off; off >>= 1) md = fmaxf(md, __shfl_xor_sync(FULL, md, off));
    float exd = dval ? __expf(ed - md) : 0.f;
    float dend = exd;
#pragma unroll
    for (int off = 16; off; off >>= 1) dend += __shfl_xor_sync(FULL, dend, off);
    float alpha = exd / dend;

    // ---------------- row gathers (bf16 rows, skip zero-weight rows) -------
    float a0 = 0.f, a1 = 0.f, a2 = 0.f, a3 = 0.f;   // ref accum (4 cols)
    float b0 = 0.f, b1 = 0.f, b2 = 0.f, b3 = 0.f;   // dir accum

#pragma unroll 8
    for (int k = 0; k < 32; k++) {
        float w = __shfl_sync(FULL, alpha, k);
        int id = __shfl_sync(FULL, didx, k);
        if (w != 0.f) {
            uint2 v = *reinterpret_cast<const uint2*>(&g_whb_dir[(size_t)id * 64 + lane * 2]);
            float2 f0 = __bfloat1622float2(*reinterpret_cast<__nv_bfloat162*>(&v.x));
            float2 f1 = __bfloat1622float2(*reinterpret_cast<__nv_bfloat162*>(&v.y));
            b0 += w * f0.x; b1 += w * f0.y; b2 += w * f1.x; b3 += w * f1.y;
        }
    }
#pragma unroll 8
    for (int k = 0; k < 32; k++) {
        float w = __shfl_sync(FULL, w1, k);
        int id = __shfl_sync(FULL, idx1, k);
        if (w != 0.f) {
            uint2 v = *reinterpret_cast<const uint2*>(&g_whb_ref[(size_t)id * 64 + lane * 2]);
            float2 f0 = __bfloat1622float2(*reinterpret_cast<__nv_bfloat162*>(&v.x));
            float2 f1 = __bfloat1622float2(*reinterpret_cast<__nv_bfloat162*>(&v.y));
            a0 += w * f0.x; a1 += w * f0.y; a2 += w * f1.x; a3 += w * f1.y;
        }
    }
#pragma unroll
    for (int k = 0; k < 8; k++) {
        float w = __shfl_sync(FULL, w2, k);
        int id = __shfl_sync(FULL, idx2, k);
        if (w != 0.f) {
            uint2 v = *reinterpret_cast<const uint2*>(&g_whb_ref[(size_t)id * 64 + lane * 2]);
            float2 f0 = __bfloat1622float2(*reinterpret_cast<__nv_bfloat162*>(&v.x));
            float2 f1 = __bfloat1622float2(*reinterpret_cast<__nv_bfloat162*>(&v.y));
            a0 += w * f0.x; a1 += w * f0.y; a2 += w * f1.x; a3 += w * f1.y;
        }
    }

    float4 o;
    o.x = 0.5f * (sigmoidf_(a0) + sigmoidf_(b0));
    o.y = 0.5f * (sigmoidf_(a1) + sigmoidf_(b1));
    o.z = 0.5f * (sigmoidf_(a2) + sigmoidf_(b2));
    o.w = 0.5f * (sigmoidf_(a3) + sigmoidf_(b3));
    *reinterpret_cast<float4*>(&out[(size_t)n * F + lane * 4]) = o;
}

// ---------------------------------------------------------------------------
extern "C" void kernel_launch(void* const* d_in, const int* in_sizes, int n_in,
                              void* d_out, int out_size)
{
    const float* h     = (const float*)d_in[0];
    const float* W_ref = (const float*)d_in[1];
    const float* a_ref = (const float*)d_in[2];
    const float* W_dir = (const float*)d_in[3];
    const float* a_dir = (const float*)d_in[4];
    const int* ref_nb  = (const int*)d_in[5];
    const int* ref_cnt = (const int*)d_in[6];
    const int* dir_nb  = (const int*)d_in[7];
    const int* dir_cnt = (const int*)d_in[8];
    float* out = (float*)d_out;

    const int N = in_sizes[0] / F;

    dim3 g1((N + 127) / 128, 2);
    gemm_tf32_kernel<<<g1, 256>>>(h, W_ref, W_dir, a_ref, a_dir, N);

    const int nwb = (N * 32 + 255) / 256;  // one warp per node
    gather_kernel<<<nwb, 256>>>(ref_nb, ref_cnt, dir_nb, dir_cnt, out, N);
}

// round 4
// speedup vs baseline: 1.7772x; 1.2038x over previous
#include <cuda_runtime.h>
#include <cuda_bf16.h>
#include <math.h>
#include <stdint.h>

#define F 128
#define MAXN 100000

// Scratch (device globals: no runtime allocation allowed)
// Wh tables stored as bf16 (2 bf16 per uint32): row = 64 uint32 = 256 B
__device__ uint32_t g_whb_ref[(size_t)MAXN * 64];
__device__ uint32_t g_whb_dir[(size_t)MAXN * 64];
__device__ float g_s_ref[MAXN];
__device__ float g_t_ref[MAXN];
__device__ float g_s_dir[MAXN];
__device__ float g_t_dir[MAXN];

__device__ __forceinline__ float leakyf(float x) { return x >= 0.f ? x : 0.2f * x; }
__device__ __forceinline__ float sigmoidf_(float x) { return 1.0f / (1.0f + __expf(-x)); }

__device__ __forceinline__ uint32_t f2tf32(float f) {
    uint32_t u;
    asm("cvt.rna.tf32.f32 %0, %1;" : "=r"(u) : "f"(f));
    return u;
}

__device__ __forceinline__ void mma_tf32(float& c0, float& c1, float& c2, float& c3,
                                         uint32_t a0, uint32_t a1, uint32_t a2, uint32_t a3,
                                         uint32_t b0, uint32_t b1) {
    asm volatile(
        "mma.sync.aligned.m16n8k8.row.col.f32.tf32.tf32.f32 "
        "{%0,%1,%2,%3},{%4,%5,%6,%7},{%8,%9},{%0,%1,%2,%3};"
        : "+f"(c0), "+f"(c1), "+f"(c2), "+f"(c3)
        : "r"(a0), "r"(a1), "r"(a2), "r"(a3), "r"(b0), "r"(b1));
}

// ---------------------------------------------------------------------------
// Kernel 1: Wh = h @ W via tf32 tensor cores. Epilogue:
//   - stores Wh as bf16x2
//   - computes s = Wh@a_self, t = Wh@a_nbr per row (fused scalars)
// ---------------------------------------------------------------------------
#define BK 16
#define LDS_STRIDE 132

__global__ __launch_bounds__(256, 2)
void gemm_tf32_kernel(const float* __restrict__ h,
                      const float* __restrict__ Wref,
                      const float* __restrict__ Wdir,
                      const float* __restrict__ a_ref,
                      const float* __restrict__ a_dir,
                      int N)
{
    const int by = blockIdx.y;
    const float* W = (by == 0) ? Wref : Wdir;
    const float* av = (by == 0) ? a_ref : a_dir;
    uint32_t* outb = (by == 0) ? g_whb_ref : g_whb_dir;
    const int m0 = blockIdx.x * 128;

    __shared__ uint32_t As[2][BK][LDS_STRIDE];  // [k][m]
    __shared__ uint32_t Bs[2][BK][LDS_STRIDE];  // [k][n]
    __shared__ float s_sm[128];
    __shared__ float t_sm[128];

    const int tid = threadIdx.x;
    const int warp = tid >> 5;
    const int lane = tid & 31;
    const int gid = lane >> 2;
    const int tig = lane & 3;
    const int wm = warp & 3;
    const int wn = warp >> 2;

    if (tid < 128) { s_sm[tid] = 0.f; t_sm[tid] = 0.f; }

    float acc[2][8][4];
#pragma unroll
    for (int i = 0; i < 2; i++)
#pragma unroll
        for (int j = 0; j < 8; j++)
#pragma unroll
            for (int r = 0; r < 4; r++) acc[i][j][r] = 0.f;

    int arow[2], ak4[2], bkr[2], bn4[2];
#pragma unroll
    for (int rep = 0; rep < 2; rep++) {
        int idx = tid + rep * 256;
        arow[rep] = idx & 127;
        ak4[rep] = idx >> 7;
        bkr[rep] = idx >> 5;
        bn4[rep] = idx & 31;
    }
    int arow_g[2];
#pragma unroll
    for (int rep = 0; rep < 2; rep++) {
        int r = m0 + arow[rep];
        arow_g[rep] = (r < N) ? r : (N - 1);
    }

    float4 aldg[2], bldg[2];
    auto issue_ldg = [&](int kt) {
#pragma unroll
        for (int rep = 0; rep < 2; rep++) {
            aldg[rep] = *reinterpret_cast<const float4*>(
                &h[(size_t)arow_g[rep] * F + kt * BK + ak4[rep] * 4]);
            bldg[rep] = *reinterpret_cast<const float4*>(
                &W[(size_t)(kt * BK + bkr[rep]) * F + bn4[rep] * 4]);
        }
    };
    auto sts = [&](int buf) {
#pragma unroll
        for (int rep = 0; rep < 2; rep++) {
            int kb = ak4[rep] * 4;
            As[buf][kb + 0][arow[rep]] = f2tf32(aldg[rep].x);
            As[buf][kb + 1][arow[rep]] = f2tf32(aldg[rep].y);
            As[buf][kb + 2][arow[rep]] = f2tf32(aldg[rep].z);
            As[buf][kb + 3][arow[rep]] = f2tf32(aldg[rep].w);
            uint4 bu;
            bu.x = f2tf32(bldg[rep].x);
            bu.y = f2tf32(bldg[rep].y);
            bu.z = f2tf32(bldg[rep].z);
            bu.w = f2tf32(bldg[rep].w);
            *reinterpret_cast<uint4*>(&Bs[buf][bkr[rep]][bn4[rep] * 4]) = bu;
        }
    };

    issue_ldg(0);
    sts(0);
    __syncthreads();

    int buf = 0;
#pragma unroll
    for (int kt = 0; kt < F / BK; ++kt) {
        if (kt < F / BK - 1) issue_ldg(kt + 1);

#pragma unroll
        for (int ks = 0; ks < 2; ks++) {
            const int kk = ks * 8;
            uint32_t afr[2][4];
#pragma unroll
            for (int mt = 0; mt < 2; mt++) {
                int mb = wm * 32 + mt * 16;
                afr[mt][0] = As[buf][kk + tig][mb + gid];
                afr[mt][1] = As[buf][kk + tig][mb + gid + 8];
                afr[mt][2] = As[buf][kk + tig + 4][mb + gid];
                afr[mt][3] = As[buf][kk + tig + 4][mb + gid + 8];
            }
#pragma unroll
            for (int nt = 0; nt < 8; nt++) {
                int nb = wn * 64 + nt * 8;
                uint32_t b0 = Bs[buf][kk + tig][nb + gid];
                uint32_t b1 = Bs[buf][kk + tig + 4][nb + gid];
#pragma unroll
                for (int mt = 0; mt < 2; mt++) {
                    mma_tf32(acc[mt][nt][0], acc[mt][nt][1], acc[mt][nt][2], acc[mt][nt][3],
                             afr[mt][0], afr[mt][1], afr[mt][2], afr[mt][3], b0, b1);
                }
            }
        }

        if (kt < F / BK - 1) {
            sts(buf ^ 1);
            __syncthreads();
            buf ^= 1;
        }
    }

    // ---- epilogue: bf16 store + fused per-row scalar dots ----
    float sp[2][2] = {{0.f, 0.f}, {0.f, 0.f}};
    float tp[2][2] = {{0.f, 0.f}, {0.f, 0.f}};

#pragma unroll
    for (int mt = 0; mt < 2; mt++) {
        int r0 = m0 + wm * 32 + mt * 16 + gid;
        int r1 = r0 + 8;
#pragma unroll
        for (int nt = 0; nt < 8; nt++) {
            int col = wn * 64 + nt * 8 + tig * 2;
            float as0 = av[col], as1 = av[col + 1];
            float an0 = av[128 + col], an1 = av[128 + col + 1];
            float c0 = acc[mt][nt][0], c1 = acc[mt][nt][1];
            float c2 = acc[mt][nt][2], c3 = acc[mt][nt][3];
            sp[mt][0] += c0 * as0 + c1 * as1;
            tp[mt][0] += c0 * an0 + c1 * an1;
            sp[mt][1] += c2 * as0 + c3 * as1;
            tp[mt][1] += c2 * an0 + c3 * an1;
            if (r0 < N) {
                __nv_bfloat162 p = __float22bfloat162_rn(make_float2(c0, c1));
                outb[(size_t)r0 * 64 + (col >> 1)] = *reinterpret_cast<uint32_t*>(&p);
            }
            if (r1 < N) {
                __nv_bfloat162 p = __float22bfloat162_rn(make_float2(c2, c3));
                outb[(size_t)r1 * 64 + (col >> 1)] = *reinterpret_cast<uint32_t*>(&p);
            }
        }
    }

#pragma unroll
    for (int mt = 0; mt < 2; mt++)
#pragma unroll
        for (int rr = 0; rr < 2; rr++) {
#pragma unroll
            for (int off = 1; off <= 2; off <<= 1) {
                sp[mt][rr] += __shfl_xor_sync(0xffffffffu, sp[mt][rr], off);
                tp[mt][rr] += __shfl_xor_sync(0xffffffffu, tp[mt][rr], off);
            }
            if (tig == 0) {
                int lr = wm * 32 + mt * 16 + gid + rr * 8;
                atomicAdd(&s_sm[lr], sp[mt][rr]);
                atomicAdd(&t_sm[lr], tp[mt][rr]);
            }
        }
    __syncthreads();

    if (tid < 128) {
        int gr = m0 + tid;
        if (gr < N) {
            if (by == 0) { g_s_ref[gr] = s_sm[tid]; g_t_ref[gr] = t_sm[tid]; }
            else         { g_s_dir[gr] = s_sm[tid]; g_t_dir[gr] = t_sm[tid]; }
        }
    }
}

// ---------------------------------------------------------------------------
// Kernel 2: fused attention + gather + sigmoid + average. One warp per node.
// Valid (weight, index) pairs are ballot-compacted to shared memory; the
// gather loop runs only over valid entries with one LDS.64 broadcast each.
// ---------------------------------------------------------------------------
__global__ __launch_bounds__(256)
void gather_kernel(const int* __restrict__ ref_nb,   // [N,4,10]
                   const int* __restrict__ ref_cnt,  // [N,4]
                   const int* __restrict__ dir_nb,   // [N,32]
                   const int* __restrict__ dir_cnt,  // [N]
                   float* __restrict__ out,
                   int N)
{
    __shared__ float redsum[8][4];
    __shared__ float2 s_ref[8][40];
    __shared__ float2 s_dir[8][32];
    const unsigned FULL = 0xffffffffu;
    const int wid = threadIdx.x >> 5;
    const int lane = threadIdx.x & 31;
    const int n = (blockIdx.x * blockDim.x + threadIdx.x) >> 5;
    if (n >= N) return;

    // ---------------- ref branch: depth-wise mean of t over valid nbrs ------
    if (lane < 4) redsum[wid][lane] = 0.f;
    __syncwarp();

    int rc_l = (lane < 4) ? ref_cnt[n * 4 + lane] : 0;
    int rcv[4];
#pragma unroll
    for (int d = 0; d < 4; d++) rcv[d] = __shfl_sync(FULL, rc_l, d);

    const int d1 = lane / 10;
    const int k1 = lane - d1 * 10;
    int idx1 = ref_nb[(size_t)n * 40 + lane];
    bool v1 = (k1 < rcv[d1]);
    if (v1) atomicAdd(&redsum[wid][d1], g_t_ref[idx1]);

    int idx2 = 0;
    bool v2 = false;
    if (lane < 8) {
        idx2 = ref_nb[(size_t)n * 40 + 32 + lane];
        v2 = ((lane + 2) < rcv[3]);
        if (v2) atomicAdd(&redsum[wid][3], g_t_ref[idx2]);
    }
    __syncwarp();

    float sref = g_s_ref[n];
    float e[4];
#pragma unroll
    for (int d = 0; d < 4; d++) {
        float cnt = (float)max(rcv[d], 1);
        e[d] = leakyf(sref + redsum[wid][d] / cnt);
    }
    float m4 = fmaxf(fmaxf(e[0], e[1]), fmaxf(e[2], e[3]));
    float ex4[4];
    float den4 = 0.f;
#pragma unroll
    for (int d = 0; d < 4; d++) { ex4[d] = __expf(e[d] - m4); den4 += ex4[d]; }
    float wd[4];
#pragma unroll
    for (int d = 0; d < 4; d++) wd[d] = ex4[d] / (den4 * (float)max(rcv[d], 1));

    float w1 = v1 ? wd[d1] : 0.f;
    float w2 = v2 ? wd[3] : 0.f;

    // ---------------- dir branch attention ---------------------------------
    int dcnt = dir_cnt[n];
    int didx = dir_nb[(size_t)n * 32 + lane];
    bool dval = (lane < dcnt);
    float sdir = g_s_dir[n];
    float ed = dval ? leakyf(sdir + g_t_dir[didx]) : -INFINITY;
    float md = ed;
#pragma unroll
    for (int off = 16; off; off >>= 1) md = fmaxf(md, __shfl_xor_sync(FULL, md, off));
    float exd = dval ? __expf(ed - md) : 0.f;
    float dend = exd;
#pragma unroll
    for (int off = 16; off; off >>= 1) dend += __shfl_xor_sync(FULL, dend, off);
    float alpha = exd / dend;

    // ---------------- ballot-compact valid (w, idx) pairs ------------------
    const unsigned lt = (1u << lane) - 1u;
    bool p1 = (w1 != 0.f);
    bool p2 = (w2 != 0.f);
    bool pdir = dval && (alpha != 0.f);
    unsigned m1 = __ballot_sync(FULL, p1);
    unsigned m2 = __ballot_sync(FULL, p2);
    unsigned mdm = __ballot_sync(FULL, pdir);
    int n1 = __popc(m1);
    int nref = n1 + __popc(m2);
    int ndir = __popc(mdm);
    if (p1) s_ref[wid][__popc(m1 & lt)] = make_float2(w1, __int_as_float(idx1));
    if (p2) s_ref[wid][n1 + __popc(m2 & lt)] = make_float2(w2, __int_as_float(idx2));
    if (pdir) s_dir[wid][__popc(mdm & lt)] = make_float2(alpha, __int_as_float(didx));
    __syncwarp();

    // ---------------- gathers over compacted lists -------------------------
    const int coff = lane * 2;  // uint32 offset within 64-word row
    float a0 = 0.f, a1 = 0.f, a2 = 0.f, a3 = 0.f;   // ref accum
    float b0 = 0.f, b1 = 0.f, b2 = 0.f, b3 = 0.f;   // dir accum

    int k = 0;
    for (; k + 2 <= ndir; k += 2) {
        float2 pA = s_dir[wid][k];
        float2 pB = s_dir[wid][k + 1];
        uint2 vA = *reinterpret_cast<const uint2*>(
            &g_whb_dir[(size_t)__float_as_int(pA.y) * 64 + coff]);
        uint2 vB = *reinterpret_cast<const uint2*>(
            &g_whb_dir[(size_t)__float_as_int(pB.y) * 64 + coff]);
        float2 fA0 = __bfloat1622float2(*reinterpret_cast<__nv_bfloat162*>(&vA.x));
        float2 fA1 = __bfloat1622float2(*reinterpret_cast<__nv_bfloat162*>(&vA.y));
        float2 fB0 = __bfloat1622float2(*reinterpret_cast<__nv_bfloat162*>(&vB.x));
        float2 fB1 = __bfloat1622float2(*reinterpret_cast<__nv_bfloat162*>(&vB.y));
        b0 += pA.x * fA0.x + pB.x * fB0.x;
        b1 += pA.x * fA0.y + pB.x * fB0.y;
        b2 += pA.x * fA1.x + pB.x * fB1.x;
        b3 += pA.x * fA1.y + pB.x * fB1.y;
    }
    if (k < ndir) {
        float2 p = s_dir[wid][k];
        uint2 v = *reinterpret_cast<const uint2*>(
            &g_whb_dir[(size_t)__float_as_int(p.y) * 64 + coff]);
        float2 f0 = __bfloat1622float2(*reinterpret_cast<__nv_bfloat162*>(&v.x));
        float2 f1 = __bfloat1622float2(*reinterpret_cast<__nv_bfloat162*>(&v.y));
        b0 += p.x * f0.x; b1 += p.x * f0.y; b2 += p.x * f1.x; b3 += p.x * f1.y;
    }

    k = 0;
    for (; k + 2 <= nref; k += 2) {
        float2 pA = s_ref[wid][k];
        float2 pB = s_ref[wid][k + 1];
        uint2 vA = *reinterpret_cast<const uint2*>(
            &g_whb_ref[(size_t)__float_as_int(pA.y) * 64 + coff]);
        uint2 vB = *reinterpret_cast<const uint2*>(
            &g_whb_ref[(size_t)__float_as_int(pB.y) * 64 + coff]);
        float2 fA0 = __bfloat1622float2(*reinterpret_cast<__nv_bfloat162*>(&vA.x));
        float2 fA1 = __bfloat1622float2(*reinterpret_cast<__nv_bfloat162*>(&vA.y));
        float2 fB0 = __bfloat1622float2(*reinterpret_cast<__nv_bfloat162*>(&vB.x));
        float2 fB1 = __bfloat1622float2(*reinterpret_cast<__nv_bfloat162*>(&vB.y));
        a0 += pA.x * fA0.x + pB.x * fB0.x;
        a1 += pA.x * fA0.y + pB.x * fB0.y;
        a2 += pA.x * fA1.x + pB.x * fB1.x;
        a3 += pA.x * fA1.y + pB.x * fB1.y;
    }
    if (k < nref) {
        float2 p = s_ref[wid][k];
        uint2 v = *reinterpret_cast<const uint2*>(
            &g_whb_ref[(size_t)__float_as_int(p.y) * 64 + coff]);
        float2 f0 = __bfloat1622float2(*reinterpret_cast<__nv_bfloat162*>(&v.x));
        float2 f1 = __bfloat1622float2(*reinterpret_cast<__nv_bfloat162*>(&v.y));
        a0 += p.x * f0.x; a1 += p.x * f0.y; a2 += p.x * f1.x; a3 += p.x * f1.y;
    }

    float4 o;
    o.x = 0.5f * (sigmoidf_(a0) + sigmoidf_(b0));
    o.y = 0.5f * (sigmoidf_(a1) + sigmoidf_(b1));
    o.z = 0.5f * (sigmoidf_(a2) + sigmoidf_(b2));
    o.w = 0.5f * (sigmoidf_(a3) + sigmoidf_(b3));
    *reinterpret_cast<float4*>(&out[(size_t)n * F + lane * 4]) = o;
}

// ---------------------------------------------------------------------------
extern "C" void kernel_launch(void* const* d_in, const int* in_sizes, int n_in,
                              void* d_out, int out_size)
{
    const float* h     = (const float*)d_in[0];
    const float* W_ref = (const float*)d_in[1];
    const float* a_ref = (const float*)d_in[2];
    const float* W_dir = (const float*)d_in[3];
    const float* a_dir = (const float*)d_in[4];
    const int* ref_nb  = (const int*)d_in[5];
    const int* ref_cnt = (const int*)d_in[6];
    const int* dir_nb  = (const int*)d_in[7];
    const int* dir_cnt = (const int*)d_in[8];
    float* out = (float*)d_out;

    const int N = in_sizes[0] / F;

    dim3 g1((N + 127) / 128, 2);
    gemm_tf32_kernel<<<g1, 256>>>(h, W_ref, W_dir, a_ref, a_dir, N);

    const int nwb = (N * 32 + 255) / 256;  // one warp per node
    gather_kernel<<<nwb, 256>>>(ref_nb, ref_cnt, dir_nb, dir_cnt, out, N);
}